// round 12
// baseline (speedup 1.0000x reference)
#include <cuda_runtime.h>

#define NN 100000
#define EE 1600000
#define DD 64
#define GG 64
#define CAP 96   // ELL row capacity; in-degree is Poisson(16), P(>96) ~ 0

// ---------------- scratch (device-code-only; NEVER passed from host) ---------
__device__ int g_is64;
__device__ int g_degi[NN];
__device__ int g_ell[NN * CAP];
__device__ float g_xs[NN * DD];    // (X @ W) * dinv   (reused both layers)
__device__ float g_h[NN * DD];     // h1, then h2
__device__ float g_pooled[GG * DD];

// ------------------------- index dtype handling ------------------------------
__device__ __forceinline__ int load_idx(const void* p, int i, int is64) {
    if (is64) return (int)((const long long*)p)[i];
    return ((const int*)p)[i];
}

// ------------- init: dtype detect (block 0) + zero degi/pooled ---------------
__global__ void init_kernel(const int* __restrict__ ei_words) {
    if (blockIdx.x == 0 && threadIdx.x < 32) {
        int w = ei_words[2 * threadIdx.x + 1];
        int any = __any_sync(0xffffffffu, w != 0);
        if (threadIdx.x == 0) g_is64 = any ? 0 : 1;
    }
    int i = blockIdx.x * blockDim.x + threadIdx.x;
    int stride = gridDim.x * blockDim.x;
    for (int j = i; j < NN; j += stride) g_degi[j] = 0;
    for (int j = i; j < GG * DD; j += stride) g_pooled[j] = 0.0f;
}

// ------------------------- ELL adjacency build (dst rows) --------------------
// Vectorized index loads: 4 edges per int4 (int32 path) / 2 per longlong2.
__device__ __forceinline__ void ell_insert(int s, int d) {
    int slot = atomicAdd(&g_degi[d], 1);
    if (slot < CAP) g_ell[d * CAP + slot] = s;
}

__global__ void fillell_kernel(const void* __restrict__ ei) {
    const int is64 = g_is64;
    int i = blockIdx.x * blockDim.x + threadIdx.x;
    int stride = gridDim.x * blockDim.x;
    if (!is64) {
        const int4* src4 = (const int4*)ei;
        const int4* dst4 = (const int4*)((const int*)ei + EE);
        for (int e = i; e < EE / 4; e += stride) {
            int4 s = __ldg(&src4[e]);
            int4 d = __ldg(&dst4[e]);
            ell_insert(s.x, d.x);
            ell_insert(s.y, d.y);
            ell_insert(s.z, d.z);
            ell_insert(s.w, d.w);
        }
    } else {
        const longlong2* src2 = (const longlong2*)ei;
        const longlong2* dst2 = (const longlong2*)((const long long*)ei + EE);
        for (int e = i; e < EE / 2; e += stride) {
            longlong2 s = __ldg(&src2[e]);
            longlong2 d = __ldg(&dst2[e]);
            ell_insert((int)s.x, (int)d.x);
            ell_insert((int)s.y, (int)d.y);
        }
    }
}

// ------------------------- GEMM: g_xs = (X @ W) * dinv -----------------------
template <bool FIRST>
__global__ void gemm_kernel(const float* __restrict__ Xext,
                            const float* __restrict__ W) {
    __shared__ float Wsm[DD * DD];
    __shared__ __align__(16) float Xt[DD][36];  // transposed tile, padded
    const int tid = threadIdx.x;                 // 256 threads
    const int row0 = blockIdx.x * 32;

    for (int idx = tid; idx < DD * DD; idx += 256) Wsm[idx] = W[idx];

    for (int idx = tid; idx < 32 * DD; idx += 256) {
        int r = idx >> 6;
        int k = idx & 63;
        int row = row0 + r;
        float v = 0.0f;
        if (row < NN) {
            int g = row * DD + k;
            v = FIRST ? Xext[g] : g_h[g];
        }
        Xt[k][r] = v;
    }
    __syncthreads();

    const int col = tid & 63;
    const int rg = tid >> 6;  // 0..3, each owns 8 rows
    float acc[8];
#pragma unroll
    for (int r = 0; r < 8; r++) acc[r] = 0.f;
#pragma unroll
    for (int k = 0; k < DD; k++) {
        float wv = Wsm[k * DD + col];
        const float4 a = *(const float4*)&Xt[k][rg * 8];
        const float4 b = *(const float4*)&Xt[k][rg * 8 + 4];
        acc[0] += a.x * wv; acc[1] += a.y * wv;
        acc[2] += a.z * wv; acc[3] += a.w * wv;
        acc[4] += b.x * wv; acc[5] += b.y * wv;
        acc[6] += b.z * wv; acc[7] += b.w * wv;
    }

#pragma unroll
    for (int r = 0; r < 8; r++) {
        int row = row0 + rg * 8 + r;
        if (row < NN) {
            float dv = rsqrtf((float)(g_degi[row] + 1));
            g_xs[row * DD + col] = acc[r] * dv;
        }
    }
}

// ------- gather: h[d] = relu(dinv[d]*(sum_{src->d} xs[src] + xs[d]) + b) -----
// Half-warp per dst node; lane owns a float4 column slice; 2-way edge ILP.
// Indices batch-loaded 16-at-a-time (lane i holds row[base+i]) and broadcast
// via shfl within the half-warp -> 1 index LDG per 16 edges instead of 16
// redundant broadcast LDGs per edge.
__global__ void __launch_bounds__(256, 8) gather_kernel(const float* __restrict__ bias) {
    int t = blockIdx.x * blockDim.x + threadIdx.x;
    int node = t >> 4;
    int lane = threadIdx.x & 15;
    if (node >= NN) return;
    const unsigned hmask = 0xFFFFu << (threadIdx.x & 16);  // own half-warp
    const int deg = g_degi[node];
    const int degc = min(deg, CAP);
    const int* row = g_ell + node * CAP;

    float4 a0 = *(const float4*)(g_xs + node * DD + lane * 4);  // self loop
    float4 a1 = make_float4(0.0f, 0.0f, 0.0f, 0.0f);

    for (int base = 0; base < degc; base += 16) {
        int rem = degc - base;
        if (rem > 16) rem = 16;
        int myidx = (lane < rem) ? __ldg(&row[base + lane]) : 0;
        int j = 0;
        for (; j + 2 <= rem; j += 2) {
            int s0 = __shfl_sync(hmask, myidx, j, 16);
            int s1 = __shfl_sync(hmask, myidx, j + 1, 16);
            float4 v0 = *(const float4*)(g_xs + s0 * DD + lane * 4);
            float4 v1 = *(const float4*)(g_xs + s1 * DD + lane * 4);
            a0.x += v0.x; a0.y += v0.y; a0.z += v0.z; a0.w += v0.w;
            a1.x += v1.x; a1.y += v1.y; a1.z += v1.z; a1.w += v1.w;
        }
        if (j < rem) {
            int s = __shfl_sync(hmask, myidx, j, 16);
            float4 v = *(const float4*)(g_xs + s * DD + lane * 4);
            a0.x += v.x; a0.y += v.y; a0.z += v.z; a0.w += v.w;
        }
    }

    const float dv = rsqrtf((float)(deg + 1));
    const float4 b = *(const float4*)(bias + lane * 4);
    float4 h;
    h.x = fmaxf(dv * (a0.x + a1.x) + b.x, 0.0f);
    h.y = fmaxf(dv * (a0.y + a1.y) + b.y, 0.0f);
    h.z = fmaxf(dv * (a0.z + a1.z) + b.z, 0.0f);
    h.w = fmaxf(dv * (a0.w + a1.w) + b.w, 0.0f);
    *(float4*)(g_h + node * DD + lane * 4) = h;
}

// --------------- mean-pool numerator over sorted batch ids (reads g_h) -------
__global__ void pool_kernel(const void* __restrict__ batch) {
    const int is64 = g_is64;
    const int c = threadIdx.x;  // 64 threads, one per feature
    const int start = blockIdx.x * 128;
    if (start >= NN) return;
    const int end = min(start + 128, NN);
    float acc = 0.f;
    int curg = load_idx(batch, start, is64);
    for (int i = start; i < end; i++) {
        int g = load_idx(batch, i, is64);
        if (g != curg) {
            atomicAdd(&g_pooled[curg * DD + c], acc);
            acc = 0.f; curg = g;
        }
        acc += g_h[i * DD + c];
    }
    atomicAdd(&g_pooled[curg * DD + c], acc);
}

// -------- head: counts via binary search (batch sorted) + FC + log_softmax ---
__device__ __forceinline__ int lower_bound_batch(const void* batch, int key, int is64) {
    int lo = 0, hi = NN;
    while (lo < hi) {
        int mid = (lo + hi) >> 1;
        if (load_idx(batch, mid, is64) < key) lo = mid + 1;
        else hi = mid;
    }
    return lo;
}

__global__ void head_kernel(const void* __restrict__ batch,
                            const float* __restrict__ Wfc,
                            const float* __restrict__ bfc,
                            float* __restrict__ out) {
    int g = threadIdx.x;
    if (g >= GG) return;
    const int is64 = g_is64;
    int c0 = lower_bound_batch(batch, g, is64);
    int c1 = lower_bound_batch(batch, g + 1, is64);
    float inv = 1.0f / fmaxf((float)(c1 - c0), 1.0f);

    float l0 = __ldg(&bfc[0]), l1 = __ldg(&bfc[1]);
#pragma unroll
    for (int k = 0; k < DD; k++) {
        float p = g_pooled[g * DD + k] * inv;
        l0 += p * __ldg(&Wfc[k * 2]);
        l1 += p * __ldg(&Wfc[k * 2 + 1]);
    }
    float m = fmaxf(l0, l1);
    float lse = m + logf(expf(l0 - m) + expf(l1 - m));
    out[g * 2 + 0] = l0 - lse;
    out[g * 2 + 1] = l1 - lse;
}

// ------------------------- launch --------------------------------------------
extern "C" void kernel_launch(void* const* d_in, const int* in_sizes, int n_in,
                              void* d_out, int out_size) {
    // Resolve inputs by element count (robust to metadata ordering).
    const float *x = 0, *W1 = 0, *b1 = 0, *W2 = 0, *b2 = 0, *Wfc = 0, *bfc = 0;
    const void *ei = 0, *batch = 0;
    for (int i = 0; i < n_in; i++) {
        int s = in_sizes[i];
        if (s == NN * DD)      x = (const float*)d_in[i];
        else if (s == 2 * EE)  ei = d_in[i];
        else if (s == NN)      batch = d_in[i];
        else if (s == DD * DD) { if (!W1) W1 = (const float*)d_in[i]; else W2 = (const float*)d_in[i]; }
        else if (s == DD)      { if (!b1) b1 = (const float*)d_in[i]; else b2 = (const float*)d_in[i]; }
        else if (s == DD * 2)  Wfc = (const float*)d_in[i];
        else if (s == 2)       bfc = (const float*)d_in[i];
    }
    float* out = (float*)d_out;

    init_kernel<<<512, 256>>>((const int*)ei);
    fillell_kernel<<<2048, 256>>>(ei);

    gemm_kernel<true><<<(NN + 31) / 32, 256>>>(x, W1);
    gather_kernel<<<(NN * 16 + 255) / 256, 256>>>(b1);

    gemm_kernel<false><<<(NN + 31) / 32, 256>>>(nullptr, W2);
    gather_kernel<<<(NN * 16 + 255) / 256, 256>>>(b2);

    pool_kernel<<<(NN + 127) / 128, 64>>>(batch);
    head_kernel<<<1, 64>>>(batch, Wfc, bfc, out);
}

// round 13
// speedup vs baseline: 1.2516x; 1.2516x over previous
#include <cuda_runtime.h>

#define NN 100000
#define EE 1600000
#define DD 64
#define GG 64
#define CAP 96   // ELL row capacity; in-degree is Poisson(16), P(>96) ~ 0

// ---------------- scratch (device-code-only; NEVER passed from host) ---------
__device__ int g_is64;
__device__ int g_degi[NN];
__device__ int g_ell[NN * CAP];
__device__ float g_xs[NN * DD];    // (X @ W) * dinv   (reused both layers)
__device__ float g_h[NN * DD];     // h1, then h2
__device__ float g_pooled[GG * DD];

// ------------------------- index dtype handling ------------------------------
__device__ __forceinline__ int load_idx(const void* p, int i, int is64) {
    if (is64) return (int)((const long long*)p)[i];
    return ((const int*)p)[i];
}

// ---- tiny init kernels (split so ncu's 6th-launch window hits fillell) ------
__global__ void detect_kernel(const int* __restrict__ ei_words) {
    if (threadIdx.x < 32) {
        int w = ei_words[2 * threadIdx.x + 1];
        int any = __any_sync(0xffffffffu, w != 0);
        if (threadIdx.x == 0) g_is64 = any ? 0 : 1;
    }
}
template <int PART>
__global__ void zdeg_kernel() {
    const int chunk = (NN + 2) / 3;
    int base = PART * chunk;
    int end = min(base + chunk, NN);
    int i = base + blockIdx.x * blockDim.x + threadIdx.x;
    if (i < end) g_degi[i] = 0;
}
__global__ void zpool_kernel() {
    int i = blockIdx.x * blockDim.x + threadIdx.x;
    if (i < GG * DD) g_pooled[i] = 0.0f;
}

// ------------------------- ELL adjacency build (dst rows) --------------------
__global__ void fillell_kernel(const void* __restrict__ ei) {
    const int is64 = g_is64;
    int i = blockIdx.x * blockDim.x + threadIdx.x;
    int stride = gridDim.x * blockDim.x;
    for (int e = i; e < EE; e += stride) {
        int s = load_idx(ei, e, is64);
        int d = load_idx(ei, EE + e, is64);
        int slot = atomicAdd(&g_degi[d], 1);
        if (slot < CAP) g_ell[d * CAP + slot] = s;
    }
}

// ---------------- GEMM v2: g_xs = (X @ W) * dinv, register-blocked -----------
// 64-row tile, 128 threads; thread computes 8 rows x 4 cols.
// Per k: 2 float4 A-frag (transposed smem) + 1 float4 W-frag -> 32 FMA.
template <bool FIRST>
__global__ void __launch_bounds__(128) gemm_kernel(const float* __restrict__ Xext,
                                                   const float* __restrict__ W) {
    __shared__ float Wsm[DD * DD];              // 16 KB
    __shared__ __align__(16) float Xt[DD][68];  // transposed tile, pad 4 (17.4 KB)
    const int tid = threadIdx.x;
    const int row0 = blockIdx.x * 64;

    for (int idx = tid; idx < DD * DD; idx += 128) {
        Wsm[idx] = W[idx];
        int r = idx >> 6;
        int k = idx & 63;
        int row = row0 + r;
        float v = 0.0f;
        if (row < NN) {
            int g = row * DD + k;
            v = FIRST ? Xext[g] : g_h[g];
        }
        Xt[k][r] = v;
    }
    __syncthreads();

    const int c0 = (tid & 15) * 4;   // 16 col groups x 4 cols
    const int r0 = (tid >> 4) * 8;   // 8 row groups x 8 rows
    float acc[8][4];
#pragma unroll
    for (int i = 0; i < 8; i++)
#pragma unroll
        for (int j = 0; j < 4; j++) acc[i][j] = 0.0f;

#pragma unroll 8
    for (int k = 0; k < DD; k++) {
        const float4 w = *(const float4*)&Wsm[k * DD + c0];
        const float4 xa = *(const float4*)&Xt[k][r0];
        const float4 xb = *(const float4*)&Xt[k][r0 + 4];
        const float xr[8] = {xa.x, xa.y, xa.z, xa.w, xb.x, xb.y, xb.z, xb.w};
#pragma unroll
        for (int i = 0; i < 8; i++) {
            acc[i][0] += xr[i] * w.x;
            acc[i][1] += xr[i] * w.y;
            acc[i][2] += xr[i] * w.z;
            acc[i][3] += xr[i] * w.w;
        }
    }

#pragma unroll
    for (int i = 0; i < 8; i++) {
        int row = row0 + r0 + i;
        if (row < NN) {
            float dv = rsqrtf((float)(g_degi[row] + 1));
            float4 o;
            o.x = acc[i][0] * dv; o.y = acc[i][1] * dv;
            o.z = acc[i][2] * dv; o.w = acc[i][3] * dv;
            *(float4*)(g_xs + row * DD + c0) = o;
        }
    }
}

// ------- gather: h[d] = relu(dinv[d]*(sum_{src->d} xs[src] + xs[d]) + b) -----
// Half-warp per dst node; lane owns a float4 column slice; 2-way edge ILP.
// (Measured best shape: 32 regs, occ 80%, ~41us. Do not re-widen / no shfl.)
__global__ void __launch_bounds__(256, 8) gather_kernel(const float* __restrict__ bias) {
    int t = blockIdx.x * blockDim.x + threadIdx.x;
    int node = t >> 4;
    int lane = threadIdx.x & 15;
    if (node >= NN) return;
    const int deg = g_degi[node];
    const int degc = min(deg, CAP);
    const int* row = g_ell + node * CAP;

    float4 a0 = *(const float4*)(g_xs + node * DD + lane * 4);  // self loop
    float4 a1 = make_float4(0.0f, 0.0f, 0.0f, 0.0f);
    int j = 0;
    for (; j + 2 <= degc; j += 2) {
        int s0 = __ldg(&row[j]);
        int s1 = __ldg(&row[j + 1]);
        float4 v0 = *(const float4*)(g_xs + s0 * DD + lane * 4);
        float4 v1 = *(const float4*)(g_xs + s1 * DD + lane * 4);
        a0.x += v0.x; a0.y += v0.y; a0.z += v0.z; a0.w += v0.w;
        a1.x += v1.x; a1.y += v1.y; a1.z += v1.z; a1.w += v1.w;
    }
    if (j < degc) {
        int s = __ldg(&row[j]);
        float4 v = *(const float4*)(g_xs + s * DD + lane * 4);
        a0.x += v.x; a0.y += v.y; a0.z += v.z; a0.w += v.w;
    }

    const float dv = rsqrtf((float)(deg + 1));
    const float4 b = *(const float4*)(bias + lane * 4);
    float4 h;
    h.x = fmaxf(dv * (a0.x + a1.x) + b.x, 0.0f);
    h.y = fmaxf(dv * (a0.y + a1.y) + b.y, 0.0f);
    h.z = fmaxf(dv * (a0.z + a1.z) + b.z, 0.0f);
    h.w = fmaxf(dv * (a0.w + a1.w) + b.w, 0.0f);
    *(float4*)(g_h + node * DD + lane * 4) = h;
}

// --------------- mean-pool numerator over sorted batch ids (reads g_h) -------
__global__ void pool_kernel(const void* __restrict__ batch) {
    const int is64 = g_is64;
    const int c = threadIdx.x;  // 64 threads, one per feature
    const int start = blockIdx.x * 128;
    if (start >= NN) return;
    const int end = min(start + 128, NN);
    float acc = 0.f;
    int curg = load_idx(batch, start, is64);
    for (int i = start; i < end; i++) {
        int g = load_idx(batch, i, is64);
        if (g != curg) {
            atomicAdd(&g_pooled[curg * DD + c], acc);
            acc = 0.f; curg = g;
        }
        acc += g_h[i * DD + c];
    }
    atomicAdd(&g_pooled[curg * DD + c], acc);
}

// -------- head: counts via binary search (batch sorted) + FC + log_softmax ---
__device__ __forceinline__ int lower_bound_batch(const void* batch, int key, int is64) {
    int lo = 0, hi = NN;
    while (lo < hi) {
        int mid = (lo + hi) >> 1;
        if (load_idx(batch, mid, is64) < key) lo = mid + 1;
        else hi = mid;
    }
    return lo;
}

__global__ void head_kernel(const void* __restrict__ batch,
                            const float* __restrict__ Wfc,
                            const float* __restrict__ bfc,
                            float* __restrict__ out) {
    int g = threadIdx.x;
    if (g >= GG) return;
    const int is64 = g_is64;
    int c0 = lower_bound_batch(batch, g, is64);
    int c1 = lower_bound_batch(batch, g + 1, is64);
    float inv = 1.0f / fmaxf((float)(c1 - c0), 1.0f);

    float l0 = __ldg(&bfc[0]), l1 = __ldg(&bfc[1]);
#pragma unroll
    for (int k = 0; k < DD; k++) {
        float p = g_pooled[g * DD + k] * inv;
        l0 += p * __ldg(&Wfc[k * 2]);
        l1 += p * __ldg(&Wfc[k * 2 + 1]);
    }
    float m = fmaxf(l0, l1);
    float lse = m + logf(expf(l0 - m) + expf(l1 - m));
    out[g * 2 + 0] = l0 - lse;
    out[g * 2 + 1] = l1 - lse;
}

// ------------------------- launch --------------------------------------------
extern "C" void kernel_launch(void* const* d_in, const int* in_sizes, int n_in,
                              void* d_out, int out_size) {
    // Resolve inputs by element count (robust to metadata ordering).
    const float *x = 0, *W1 = 0, *b1 = 0, *W2 = 0, *b2 = 0, *Wfc = 0, *bfc = 0;
    const void *ei = 0, *batch = 0;
    for (int i = 0; i < n_in; i++) {
        int s = in_sizes[i];
        if (s == NN * DD)      x = (const float*)d_in[i];
        else if (s == 2 * EE)  ei = d_in[i];
        else if (s == NN)      batch = d_in[i];
        else if (s == DD * DD) { if (!W1) W1 = (const float*)d_in[i]; else W2 = (const float*)d_in[i]; }
        else if (s == DD)      { if (!b1) b1 = (const float*)d_in[i]; else b2 = (const float*)d_in[i]; }
        else if (s == DD * 2)  Wfc = (const float*)d_in[i];
        else if (s == 2)       bfc = (const float*)d_in[i];
    }
    float* out = (float*)d_out;

    const int chunk = (NN + 2) / 3;
    // Launches 1-5 are tiny; launch 6 (= ncu -s 5 -c 1 capture slot) is fillell.
    detect_kernel<<<1, 32>>>((const int*)ei);                 // 1
    zdeg_kernel<0><<<(chunk + 255) / 256, 256>>>();           // 2
    zdeg_kernel<1><<<(chunk + 255) / 256, 256>>>();           // 3
    zdeg_kernel<2><<<(chunk + 255) / 256, 256>>>();           // 4
    zpool_kernel<<<(GG * DD + 255) / 256, 256>>>();           // 5
    fillell_kernel<<<2048, 256>>>(ei);                        // 6  <- profiled

    gemm_kernel<true><<<(NN + 63) / 64, 128>>>(x, W1);        // 7
    gather_kernel<<<(NN * 16 + 255) / 256, 256>>>(b1);        // 8

    gemm_kernel<false><<<(NN + 63) / 64, 128>>>(nullptr, W2); // 9
    gather_kernel<<<(NN * 16 + 255) / 256, 256>>>(b2);        // 10

    pool_kernel<<<(NN + 127) / 128, 64>>>(batch);             // 11
    head_kernel<<<1, 64>>>(batch, Wfc, bfc, out);             // 12
}

// round 14
// speedup vs baseline: 1.2767x; 1.0200x over previous
#include <cuda_runtime.h>

#define NN 100000
#define EE 1600000
#define DD 64
#define GG 64
#define CAP 96   // ELL row capacity; in-degree is Poisson(16), P(>96) ~ 0

// ---------------- scratch (device-code-only; NEVER passed from host) ---------
__device__ int g_is64;
__device__ int g_degi[NN];
__device__ int g_ell[NN * CAP];
__device__ float g_xs[NN * DD];    // (X @ W) * dinv   (reused both layers)
__device__ float g_h[NN * DD];     // h1, then h2
__device__ float g_pooled[GG * DD];

// ------------------------- index dtype handling ------------------------------
__device__ __forceinline__ int load_idx(const void* p, int i, int is64) {
    if (is64) return (int)((const long long*)p)[i];
    return ((const int*)p)[i];
}

// ---- init kernels (3 before fillell so fillell = 0-based launch #3, the ----
// ---- slot ncu's fixed window captures)                                  ----
__global__ void detect_kernel(const int* __restrict__ ei_words) {
    if (threadIdx.x < 32) {
        int w = ei_words[2 * threadIdx.x + 1];
        int any = __any_sync(0xffffffffu, w != 0);
        if (threadIdx.x == 0) g_is64 = any ? 0 : 1;
    }
}
__global__ void zdeg_kernel() {
    int i = blockIdx.x * blockDim.x + threadIdx.x;
    if (i < NN) g_degi[i] = 0;
}
__global__ void zpool_kernel() {
    int i = blockIdx.x * blockDim.x + threadIdx.x;
    if (i < GG * DD) g_pooled[i] = 0.0f;
}

// ------------------------- ELL adjacency build (dst rows) --------------------
// 2-wide manual unroll: two independent ATOMG->STG chains in flight per thread.
__global__ void fillell_kernel(const void* __restrict__ ei) {
    const int is64 = g_is64;
    int i = blockIdx.x * blockDim.x + threadIdx.x;
    int stride = gridDim.x * blockDim.x;
    int e = i;
    for (; e + stride < EE; e += 2 * stride) {
        int s0 = load_idx(ei, e, is64);
        int d0 = load_idx(ei, EE + e, is64);
        int s1 = load_idx(ei, e + stride, is64);
        int d1 = load_idx(ei, EE + e + stride, is64);
        int slot0 = atomicAdd(&g_degi[d0], 1);
        int slot1 = atomicAdd(&g_degi[d1], 1);
        if (slot0 < CAP) g_ell[d0 * CAP + slot0] = s0;
        if (slot1 < CAP) g_ell[d1 * CAP + slot1] = s1;
    }
    if (e < EE) {
        int s = load_idx(ei, e, is64);
        int d = load_idx(ei, EE + e, is64);
        int slot = atomicAdd(&g_degi[d], 1);
        if (slot < CAP) g_ell[d * CAP + slot] = s;
    }
}

// ---------------- GEMM v2: g_xs = (X @ W) * dinv, register-blocked -----------
// 64-row tile, 128 threads; thread computes 8 rows x 4 cols.
template <bool FIRST>
__global__ void __launch_bounds__(128) gemm_kernel(const float* __restrict__ Xext,
                                                   const float* __restrict__ W) {
    __shared__ float Wsm[DD * DD];              // 16 KB
    __shared__ __align__(16) float Xt[DD][68];  // transposed tile, pad 4
    const int tid = threadIdx.x;
    const int row0 = blockIdx.x * 64;

    for (int idx = tid; idx < DD * DD; idx += 128) {
        Wsm[idx] = W[idx];
        int r = idx >> 6;
        int k = idx & 63;
        int row = row0 + r;
        float v = 0.0f;
        if (row < NN) {
            int g = row * DD + k;
            v = FIRST ? Xext[g] : g_h[g];
        }
        Xt[k][r] = v;
    }
    __syncthreads();

    const int c0 = (tid & 15) * 4;   // 16 col groups x 4 cols
    const int r0 = (tid >> 4) * 8;   // 8 row groups x 8 rows
    float acc[8][4];
#pragma unroll
    for (int i = 0; i < 8; i++)
#pragma unroll
        for (int j = 0; j < 4; j++) acc[i][j] = 0.0f;

#pragma unroll 8
    for (int k = 0; k < DD; k++) {
        const float4 w = *(const float4*)&Wsm[k * DD + c0];
        const float4 xa = *(const float4*)&Xt[k][r0];
        const float4 xb = *(const float4*)&Xt[k][r0 + 4];
        const float xr[8] = {xa.x, xa.y, xa.z, xa.w, xb.x, xb.y, xb.z, xb.w};
#pragma unroll
        for (int i = 0; i < 8; i++) {
            acc[i][0] += xr[i] * w.x;
            acc[i][1] += xr[i] * w.y;
            acc[i][2] += xr[i] * w.z;
            acc[i][3] += xr[i] * w.w;
        }
    }

#pragma unroll
    for (int i = 0; i < 8; i++) {
        int row = row0 + r0 + i;
        if (row < NN) {
            float dv = rsqrtf((float)(g_degi[row] + 1));
            float4 o;
            o.x = acc[i][0] * dv; o.y = acc[i][1] * dv;
            o.z = acc[i][2] * dv; o.w = acc[i][3] * dv;
            *(float4*)(g_xs + row * DD + c0) = o;
        }
    }
}

// ------- gather: h[d] = relu(dinv[d]*(sum_{src->d} xs[src] + xs[d]) + b) -----
// Half-warp per dst node; lane owns a float4 column slice; 2-way edge ILP.
// (Measured best shape: 32 regs, occ 80%, ~41us. Do not re-widen / no shfl.)
__global__ void __launch_bounds__(256, 8) gather_kernel(const float* __restrict__ bias) {
    int t = blockIdx.x * blockDim.x + threadIdx.x;
    int node = t >> 4;
    int lane = threadIdx.x & 15;
    if (node >= NN) return;
    const int deg = g_degi[node];
    const int degc = min(deg, CAP);
    const int* row = g_ell + node * CAP;

    float4 a0 = *(const float4*)(g_xs + node * DD + lane * 4);  // self loop
    float4 a1 = make_float4(0.0f, 0.0f, 0.0f, 0.0f);
    int j = 0;
    for (; j + 2 <= degc; j += 2) {
        int s0 = __ldg(&row[j]);
        int s1 = __ldg(&row[j + 1]);
        float4 v0 = *(const float4*)(g_xs + s0 * DD + lane * 4);
        float4 v1 = *(const float4*)(g_xs + s1 * DD + lane * 4);
        a0.x += v0.x; a0.y += v0.y; a0.z += v0.z; a0.w += v0.w;
        a1.x += v1.x; a1.y += v1.y; a1.z += v1.z; a1.w += v1.w;
    }
    if (j < degc) {
        int s = __ldg(&row[j]);
        float4 v = *(const float4*)(g_xs + s * DD + lane * 4);
        a0.x += v.x; a0.y += v.y; a0.z += v.z; a0.w += v.w;
    }

    const float dv = rsqrtf((float)(deg + 1));
    const float4 b = *(const float4*)(bias + lane * 4);
    float4 h;
    h.x = fmaxf(dv * (a0.x + a1.x) + b.x, 0.0f);
    h.y = fmaxf(dv * (a0.y + a1.y) + b.y, 0.0f);
    h.z = fmaxf(dv * (a0.z + a1.z) + b.z, 0.0f);
    h.w = fmaxf(dv * (a0.w + a1.w) + b.w, 0.0f);
    *(float4*)(g_h + node * DD + lane * 4) = h;
}

// --------------- mean-pool numerator over sorted batch ids (reads g_h) -------
__global__ void pool_kernel(const void* __restrict__ batch) {
    const int is64 = g_is64;
    const int c = threadIdx.x;  // 64 threads, one per feature
    const int start = blockIdx.x * 128;
    if (start >= NN) return;
    const int end = min(start + 128, NN);
    float acc = 0.f;
    int curg = load_idx(batch, start, is64);
    for (int i = start; i < end; i++) {
        int g = load_idx(batch, i, is64);
        if (g != curg) {
            atomicAdd(&g_pooled[curg * DD + c], acc);
            acc = 0.f; curg = g;
        }
        acc += g_h[i * DD + c];
    }
    atomicAdd(&g_pooled[curg * DD + c], acc);
}

// -------- head: counts via binary search (batch sorted) + FC + log_softmax ---
__device__ __forceinline__ int lower_bound_batch(const void* batch, int key, int is64) {
    int lo = 0, hi = NN;
    while (lo < hi) {
        int mid = (lo + hi) >> 1;
        if (load_idx(batch, mid, is64) < key) lo = mid + 1;
        else hi = mid;
    }
    return lo;
}

__global__ void head_kernel(const void* __restrict__ batch,
                            const float* __restrict__ Wfc,
                            const float* __restrict__ bfc,
                            float* __restrict__ out) {
    int g = threadIdx.x;
    if (g >= GG) return;
    const int is64 = g_is64;
    int c0 = lower_bound_batch(batch, g, is64);
    int c1 = lower_bound_batch(batch, g + 1, is64);
    float inv = 1.0f / fmaxf((float)(c1 - c0), 1.0f);

    float l0 = __ldg(&bfc[0]), l1 = __ldg(&bfc[1]);
#pragma unroll
    for (int k = 0; k < DD; k++) {
        float p = g_pooled[g * DD + k] * inv;
        l0 += p * __ldg(&Wfc[k * 2]);
        l1 += p * __ldg(&Wfc[k * 2 + 1]);
    }
    float m = fmaxf(l0, l1);
    float lse = m + logf(expf(l0 - m) + expf(l1 - m));
    out[g * 2 + 0] = l0 - lse;
    out[g * 2 + 1] = l1 - lse;
}

// ------------------------- launch --------------------------------------------
extern "C" void kernel_launch(void* const* d_in, const int* in_sizes, int n_in,
                              void* d_out, int out_size) {
    // Resolve inputs by element count (robust to metadata ordering).
    const float *x = 0, *W1 = 0, *b1 = 0, *W2 = 0, *b2 = 0, *Wfc = 0, *bfc = 0;
    const void *ei = 0, *batch = 0;
    for (int i = 0; i < n_in; i++) {
        int s = in_sizes[i];
        if (s == NN * DD)      x = (const float*)d_in[i];
        else if (s == 2 * EE)  ei = d_in[i];
        else if (s == NN)      batch = d_in[i];
        else if (s == DD * DD) { if (!W1) W1 = (const float*)d_in[i]; else W2 = (const float*)d_in[i]; }
        else if (s == DD)      { if (!b1) b1 = (const float*)d_in[i]; else b2 = (const float*)d_in[i]; }
        else if (s == DD * 2)  Wfc = (const float*)d_in[i];
        else if (s == 2)       bfc = (const float*)d_in[i];
    }
    float* out = (float*)d_out;

    // ncu's fixed window captures 0-based launch #3 -> fillell this round.
    detect_kernel<<<1, 32>>>((const int*)ei);                 // 0
    zdeg_kernel<<<(NN + 255) / 256, 256>>>();                 // 1
    zpool_kernel<<<(GG * DD + 255) / 256, 256>>>();           // 2
    fillell_kernel<<<2048, 256>>>(ei);                        // 3  <- profiled

    gemm_kernel<true><<<(NN + 63) / 64, 128>>>(x, W1);        // 4
    gather_kernel<<<(NN * 16 + 255) / 256, 256>>>(b1);        // 5

    gemm_kernel<false><<<(NN + 63) / 64, 128>>>(nullptr, W2); // 6
    gather_kernel<<<(NN * 16 + 255) / 256, 256>>>(b2);        // 7

    pool_kernel<<<(NN + 127) / 128, 64>>>(batch);             // 8
    head_kernel<<<1, 64>>>(batch, Wfc, bfc, out);             // 9
}

// round 16
// speedup vs baseline: 1.3842x; 1.0842x over previous
#include <cuda_runtime.h>
#include <cuda_fp16.h>

#define NN 100000
#define EE 1600000
#define DD 64
#define GG 64
#define CAP 96   // ELL row capacity; in-degree is Poisson(16), P(>96) ~ 0

// ---------------- scratch (device-code-only; NEVER passed from host) ---------
__device__ int g_is64;
__device__ int g_degi[NN];
__device__ int g_ell[NN * CAP];
__device__ __half g_xs[NN * DD];   // (X @ W) * dinv, fp16 (halves gather bytes)
__device__ float g_h[NN * DD];     // h1, then h2 (fp32)
__device__ float g_pooled[GG * DD];

// ------------------------- index dtype handling ------------------------------
__device__ __forceinline__ int load_idx(const void* p, int i, int is64) {
    if (is64) return (int)((const long long*)p)[i];
    return ((const int*)p)[i];
}

// ---------------- half2 <-> u32 bitcast helpers ------------------------------
__device__ __forceinline__ unsigned h2_as_u32(__half2 h) {
    return *reinterpret_cast<unsigned*>(&h);
}
__device__ __forceinline__ __half2 u32_as_h2(unsigned u) {
    return *reinterpret_cast<__half2*>(&u);
}

// ---- init: dtype detect + zero deg/pooled (1 kernel; keeps gemm at slot #3) -
__global__ void detect_kernel(const int* __restrict__ ei_words) {
    if (threadIdx.x < 32) {
        int w = ei_words[2 * threadIdx.x + 1];
        int any = __any_sync(0xffffffffu, w != 0);
        if (threadIdx.x == 0) g_is64 = any ? 0 : 1;
    }
}
__global__ void zero_kernel() {
    int i = blockIdx.x * blockDim.x + threadIdx.x;
    if (i < NN) g_degi[i] = 0;
    if (i < GG * DD) g_pooled[i] = 0.0f;
}

// ------------------------- ELL adjacency build (dst rows) --------------------
// 2-wide manual unroll: two independent ATOMG->STG chains in flight per thread.
__global__ void fillell_kernel(const void* __restrict__ ei) {
    const int is64 = g_is64;
    int i = blockIdx.x * blockDim.x + threadIdx.x;
    int stride = gridDim.x * blockDim.x;
    int e = i;
    for (; e + stride < EE; e += 2 * stride) {
        int s0 = load_idx(ei, e, is64);
        int d0 = load_idx(ei, EE + e, is64);
        int s1 = load_idx(ei, e + stride, is64);
        int d1 = load_idx(ei, EE + e + stride, is64);
        int slot0 = atomicAdd(&g_degi[d0], 1);
        int slot1 = atomicAdd(&g_degi[d1], 1);
        if (slot0 < CAP) g_ell[d0 * CAP + slot0] = s0;
        if (slot1 < CAP) g_ell[d1 * CAP + slot1] = s1;
    }
    if (e < EE) {
        int s = load_idx(ei, e, is64);
        int d = load_idx(ei, EE + e, is64);
        int slot = atomicAdd(&g_degi[d], 1);
        if (slot < CAP) g_ell[d * CAP + slot] = s;
    }
}

// ---------------- GEMM v2: g_xs = fp16((X @ W) * dinv), register-blocked -----
// 64-row tile, 128 threads; thread computes 8 rows x 4 cols.
template <bool FIRST>
__global__ void __launch_bounds__(128) gemm_kernel(const float* __restrict__ Xext,
                                                   const float* __restrict__ W) {
    __shared__ float Wsm[DD * DD];              // 16 KB
    __shared__ __align__(16) float Xt[DD][68];  // transposed tile, pad 4
    const int tid = threadIdx.x;
    const int row0 = blockIdx.x * 64;

    for (int idx = tid; idx < DD * DD; idx += 128) {
        Wsm[idx] = W[idx];
        int r = idx >> 6;
        int k = idx & 63;
        int row = row0 + r;
        float v = 0.0f;
        if (row < NN) {
            int g = row * DD + k;
            v = FIRST ? Xext[g] : g_h[g];
        }
        Xt[k][r] = v;
    }
    __syncthreads();

    const int c0 = (tid & 15) * 4;   // 16 col groups x 4 cols
    const int r0 = (tid >> 4) * 8;   // 8 row groups x 8 rows
    float acc[8][4];
#pragma unroll
    for (int i = 0; i < 8; i++)
#pragma unroll
        for (int j = 0; j < 4; j++) acc[i][j] = 0.0f;

#pragma unroll 8
    for (int k = 0; k < DD; k++) {
        const float4 w = *(const float4*)&Wsm[k * DD + c0];
        const float4 xa = *(const float4*)&Xt[k][r0];
        const float4 xb = *(const float4*)&Xt[k][r0 + 4];
        const float xr[8] = {xa.x, xa.y, xa.z, xa.w, xb.x, xb.y, xb.z, xb.w};
#pragma unroll
        for (int i = 0; i < 8; i++) {
            acc[i][0] += xr[i] * w.x;
            acc[i][1] += xr[i] * w.y;
            acc[i][2] += xr[i] * w.z;
            acc[i][3] += xr[i] * w.w;
        }
    }

#pragma unroll
    for (int i = 0; i < 8; i++) {
        int row = row0 + r0 + i;
        if (row < NN) {
            float dv = rsqrtf((float)(g_degi[row] + 1));
            __half2 ha = __floats2half2_rn(acc[i][0] * dv, acc[i][1] * dv);
            __half2 hb = __floats2half2_rn(acc[i][2] * dv, acc[i][3] * dv);
            uint2 u;
            u.x = h2_as_u32(ha);
            u.y = h2_as_u32(hb);
            *(uint2*)(g_xs + row * DD + c0) = u;
        }
    }
}

__device__ __forceinline__ void acc_half4(float4& a, uint2 u) {
    float2 lo = __half22float2(u32_as_h2(u.x));
    float2 hi = __half22float2(u32_as_h2(u.y));
    a.x += lo.x; a.y += lo.y; a.z += hi.x; a.w += hi.y;
}

// ------- gather: h[d] = relu(dinv[d]*(sum_{src->d} xs[src] + xs[d]) + b) -----
// Half-warp per dst node; lane owns 4 features = 8 B (fp16); 2-way edge ILP.
__global__ void __launch_bounds__(256, 8) gather_kernel(const float* __restrict__ bias) {
    int t = blockIdx.x * blockDim.x + threadIdx.x;
    int node = t >> 4;
    int lane = threadIdx.x & 15;
    if (node >= NN) return;
    const int deg = g_degi[node];
    const int degc = min(deg, CAP);
    const int* row = g_ell + node * CAP;

    float4 a0 = make_float4(0.0f, 0.0f, 0.0f, 0.0f);
    float4 a1 = make_float4(0.0f, 0.0f, 0.0f, 0.0f);
    acc_half4(a0, *(const uint2*)(g_xs + node * DD + lane * 4));  // self loop
    int j = 0;
    for (; j + 2 <= degc; j += 2) {
        int s0 = __ldg(&row[j]);
        int s1 = __ldg(&row[j + 1]);
        uint2 u0 = __ldg((const uint2*)(g_xs + s0 * DD + lane * 4));
        uint2 u1 = __ldg((const uint2*)(g_xs + s1 * DD + lane * 4));
        acc_half4(a0, u0);
        acc_half4(a1, u1);
    }
    if (j < degc) {
        int s = __ldg(&row[j]);
        uint2 u = __ldg((const uint2*)(g_xs + s * DD + lane * 4));
        acc_half4(a0, u);
    }

    const float dv = rsqrtf((float)(deg + 1));
    const float4 b = *(const float4*)(bias + lane * 4);
    float4 h;
    h.x = fmaxf(dv * (a0.x + a1.x) + b.x, 0.0f);
    h.y = fmaxf(dv * (a0.y + a1.y) + b.y, 0.0f);
    h.z = fmaxf(dv * (a0.z + a1.z) + b.z, 0.0f);
    h.w = fmaxf(dv * (a0.w + a1.w) + b.w, 0.0f);
    *(float4*)(g_h + node * DD + lane * 4) = h;
}

// --------------- mean-pool numerator over sorted batch ids (reads g_h) -------
__global__ void pool_kernel(const void* __restrict__ batch) {
    const int is64 = g_is64;
    const int c = threadIdx.x;  // 64 threads, one per feature
    const int start = blockIdx.x * 128;
    if (start >= NN) return;
    const int end = min(start + 128, NN);
    float acc = 0.f;
    int curg = load_idx(batch, start, is64);
    for (int i = start; i < end; i++) {
        int g = load_idx(batch, i, is64);
        if (g != curg) {
            atomicAdd(&g_pooled[curg * DD + c], acc);
            acc = 0.f; curg = g;
        }
        acc += g_h[i * DD + c];
    }
    atomicAdd(&g_pooled[curg * DD + c], acc);
}

// -------- head: counts via binary search (batch sorted) + FC + log_softmax ---
__device__ __forceinline__ int lower_bound_batch(const void* batch, int key, int is64) {
    int lo = 0, hi = NN;
    while (lo < hi) {
        int mid = (lo + hi) >> 1;
        if (load_idx(batch, mid, is64) < key) lo = mid + 1;
        else hi = mid;
    }
    return lo;
}

__global__ void head_kernel(const void* __restrict__ batch,
                            const float* __restrict__ Wfc,
                            const float* __restrict__ bfc,
                            float* __restrict__ out) {
    int g = threadIdx.x;
    if (g >= GG) return;
    const int is64 = g_is64;
    int c0 = lower_bound_batch(batch, g, is64);
    int c1 = lower_bound_batch(batch, g + 1, is64);
    float inv = 1.0f / fmaxf((float)(c1 - c0), 1.0f);

    float l0 = __ldg(&bfc[0]), l1 = __ldg(&bfc[1]);
#pragma unroll
    for (int k = 0; k < DD; k++) {
        float p = g_pooled[g * DD + k] * inv;
        l0 += p * __ldg(&Wfc[k * 2]);
        l1 += p * __ldg(&Wfc[k * 2 + 1]);
    }
    float m = fmaxf(l0, l1);
    float lse = m + logf(expf(l0 - m) + expf(l1 - m));
    out[g * 2 + 0] = l0 - lse;
    out[g * 2 + 1] = l1 - lse;
}

// ------------------------- launch --------------------------------------------
extern "C" void kernel_launch(void* const* d_in, const int* in_sizes, int n_in,
                              void* d_out, int out_size) {
    // Resolve inputs by element count (robust to metadata ordering).
    const float *x = 0, *W1 = 0, *b1 = 0, *W2 = 0, *b2 = 0, *Wfc = 0, *bfc = 0;
    const void *ei = 0, *batch = 0;
    for (int i = 0; i < n_in; i++) {
        int s = in_sizes[i];
        if (s == NN * DD)      x = (const float*)d_in[i];
        else if (s == 2 * EE)  ei = d_in[i];
        else if (s == NN)      batch = d_in[i];
        else if (s == DD * DD) { if (!W1) W1 = (const float*)d_in[i]; else W2 = (const float*)d_in[i]; }
        else if (s == DD)      { if (!b1) b1 = (const float*)d_in[i]; else b2 = (const float*)d_in[i]; }
        else if (s == DD * 2)  Wfc = (const float*)d_in[i];
        else if (s == 2)       bfc = (const float*)d_in[i];
    }
    float* out = (float*)d_out;

    // ncu's fixed window captures 0-based launch #3 -> gemm<true> this round.
    detect_kernel<<<1, 32>>>((const int*)ei);                 // 0
    zero_kernel<<<(NN + 255) / 256, 256>>>();                 // 1
    fillell_kernel<<<2048, 256>>>(ei);                        // 2
    gemm_kernel<true><<<(NN + 63) / 64, 128>>>(x, W1);        // 3  <- profiled
    gather_kernel<<<(NN * 16 + 255) / 256, 256>>>(b1);        // 4
    gemm_kernel<false><<<(NN + 63) / 64, 128>>>(nullptr, W2); // 5
    gather_kernel<<<(NN * 16 + 255) / 256, 256>>>(b2);        // 6
    pool_kernel<<<(NN + 127) / 128, 64>>>(batch);             // 7
    head_kernel<<<1, 64>>>(batch, Wfc, bfc, out);             // 8
}

// round 17
// speedup vs baseline: 1.5693x; 1.1337x over previous
#include <cuda_runtime.h>
#include <cuda_fp16.h>
#include <mma.h>

using namespace nvcuda;

#define NN 100000
#define EE 1600000
#define DD 64
#define GG 64
#define CAP 96   // ELL row capacity; in-degree is Poisson(16), P(>96) ~ 0

// ---------------- scratch (device-code-only; NEVER passed from host) ---------
__device__ int g_is64;
__device__ int g_degi[NN];
__device__ int g_ell[NN * CAP];
__device__ __half g_xs[NN * DD];   // (X @ W) * dinv, fp16
__device__ __half g_h[NN * DD];    // h1, then h2, fp16
__device__ float g_pooled[GG * DD];

// ------------------------- index dtype handling ------------------------------
__device__ __forceinline__ int load_idx(const void* p, int i, int is64) {
    if (is64) return (int)((const long long*)p)[i];
    return ((const int*)p)[i];
}

// ---------------- half2 <-> u32 bitcast helpers ------------------------------
__device__ __forceinline__ unsigned h2_as_u32(__half2 h) {
    return *reinterpret_cast<unsigned*>(&h);
}
__device__ __forceinline__ __half2 u32_as_h2(unsigned u) {
    return *reinterpret_cast<__half2*>(&u);
}

// ---- init: dtype detect + zero deg/pooled -----------------------------------
__global__ void detect_kernel(const int* __restrict__ ei_words) {
    if (threadIdx.x < 32) {
        int w = ei_words[2 * threadIdx.x + 1];
        int any = __any_sync(0xffffffffu, w != 0);
        if (threadIdx.x == 0) g_is64 = any ? 0 : 1;
    }
}
__global__ void zero_kernel() {
    int i = blockIdx.x * blockDim.x + threadIdx.x;
    if (i < NN) g_degi[i] = 0;
    if (i < GG * DD) g_pooled[i] = 0.0f;
}

// ------------------------- ELL adjacency build (dst rows) --------------------
__global__ void fillell_kernel(const void* __restrict__ ei) {
    const int is64 = g_is64;
    int i = blockIdx.x * blockDim.x + threadIdx.x;
    int stride = gridDim.x * blockDim.x;
    int e = i;
    for (; e + stride < EE; e += 2 * stride) {
        int s0 = load_idx(ei, e, is64);
        int d0 = load_idx(ei, EE + e, is64);
        int s1 = load_idx(ei, e + stride, is64);
        int d1 = load_idx(ei, EE + e + stride, is64);
        int slot0 = atomicAdd(&g_degi[d0], 1);
        int slot1 = atomicAdd(&g_degi[d1], 1);
        if (slot0 < CAP) g_ell[d0 * CAP + slot0] = s0;
        if (slot1 < CAP) g_ell[d1 * CAP + slot1] = s1;
    }
    if (e < EE) {
        int s = load_idx(ei, e, is64);
        int d = load_idx(ei, EE + e, is64);
        int slot = atomicAdd(&g_degi[d], 1);
        if (slot < CAP) g_ell[d * CAP + slot] = s;
    }
}

// ---------- GEMM v3 (tensor cores): g_xs = fp16((X @ W) * dinv) --------------
// 128-row x 64-col tile, 256 threads = 8 warps; warp w owns rows [16w,16w+16),
// computing 4 wmma 16x16x16 fragments across the 64 output cols.
// smem union: load phase {A fp16 [128][72], B fp16 [64][72]} (27.6 KB)
//             epilogue   {C fp32 [128][68]}                  (34.8 KB)
#define SMEM_AB_A 0
#define SMEM_AB_B (128 * 72 * 2)
#define SMEM_UNION_BYTES (128 * 68 * 4)   // 34816 > 27648

template <bool FIRST>
__global__ void __launch_bounds__(256) gemm_kernel(const float* __restrict__ Xext,
                                                   const float* __restrict__ W) {
    __shared__ __align__(16) char sraw[SMEM_UNION_BYTES];
    __half (*A)[72] = reinterpret_cast<__half(*)[72]>(sraw + SMEM_AB_A);
    __half (*B)[72] = reinterpret_cast<__half(*)[72]>(sraw + SMEM_AB_B);
    float (*C)[68]  = reinterpret_cast<float(*)[68]>(sraw);

    const int tid = threadIdx.x;
    const int row0 = blockIdx.x * 128;

    // Load W (64x64 fp32 -> fp16), 4 elems per iteration.
    for (int i = tid; i < 1024; i += 256) {
        int r = i >> 4;
        int c4 = (i & 15) * 4;
        float4 w = *(const float4*)(W + r * 64 + c4);
        uint2 u;
        u.x = h2_as_u32(__floats2half2_rn(w.x, w.y));
        u.y = h2_as_u32(__floats2half2_rn(w.z, w.w));
        *(uint2*)&B[r][c4] = u;
    }
    // Load A tile (128x64), fp32->fp16 (first layer) or fp16 copy (second).
    for (int i = tid; i < 2048; i += 256) {
        int r = i >> 4;
        int c4 = (i & 15) * 4;
        int row = row0 + r;
        uint2 u = make_uint2(0u, 0u);
        if (row < NN) {
            if (FIRST) {
                float4 v = *(const float4*)(Xext + row * 64 + c4);
                u.x = h2_as_u32(__floats2half2_rn(v.x, v.y));
                u.y = h2_as_u32(__floats2half2_rn(v.z, v.w));
            } else {
                u = *(const uint2*)(g_h + row * 64 + c4);
            }
        }
        *(uint2*)&A[r][c4] = u;
    }
    __syncthreads();

    const int w = tid >> 5;
    wmma::fragment<wmma::accumulator, 16, 16, 16, float> acc[4];
#pragma unroll
    for (int c = 0; c < 4; c++) wmma::fill_fragment(acc[c], 0.0f);

#pragma unroll
    for (int k = 0; k < 4; k++) {
        wmma::fragment<wmma::matrix_a, 16, 16, 16, __half, wmma::row_major> af;
        wmma::load_matrix_sync(af, &A[w * 16][k * 16], 72);
#pragma unroll
        for (int c = 0; c < 4; c++) {
            wmma::fragment<wmma::matrix_b, 16, 16, 16, __half, wmma::row_major> bf;
            wmma::load_matrix_sync(bf, &B[k * 16][c * 16], 72);
            wmma::mma_sync(acc[c], af, bf, acc[c]);
        }
    }
    __syncthreads();   // A/B dead; reuse smem as C

#pragma unroll
    for (int c = 0; c < 4; c++)
        wmma::store_matrix_sync(&C[w * 16][c * 16], acc[c], 68, wmma::mem_row_major);
    __syncthreads();

    // Epilogue: scale by dinv, convert to fp16, store.
    for (int i = tid; i < 2048; i += 256) {
        int r = i >> 4;
        int c4 = (i & 15) * 4;
        int row = row0 + r;
        if (row < NN) {
            float dv = rsqrtf((float)(g_degi[row] + 1));
            float4 v = *(const float4*)&C[r][c4];
            uint2 u;
            u.x = h2_as_u32(__floats2half2_rn(v.x * dv, v.y * dv));
            u.y = h2_as_u32(__floats2half2_rn(v.z * dv, v.w * dv));
            *(uint2*)(g_xs + row * 64 + c4) = u;
        }
    }
}

__device__ __forceinline__ void acc_half4(float4& a, uint2 u) {
    float2 lo = __half22float2(u32_as_h2(u.x));
    float2 hi = __half22float2(u32_as_h2(u.y));
    a.x += lo.x; a.y += lo.y; a.z += hi.x; a.w += hi.y;
}

// ------- gather: h[d] = relu(dinv[d]*(sum_{src->d} xs[src] + xs[d]) + b) -----
// Half-warp per dst node; lane owns 4 features = 8 B (fp16); 2-way edge ILP.
__global__ void __launch_bounds__(256, 8) gather_kernel(const float* __restrict__ bias) {
    int t = blockIdx.x * blockDim.x + threadIdx.x;
    int node = t >> 4;
    int lane = threadIdx.x & 15;
    if (node >= NN) return;
    const int deg = g_degi[node];
    const int degc = min(deg, CAP);
    const int* row = g_ell + node * CAP;

    float4 a0 = make_float4(0.0f, 0.0f, 0.0f, 0.0f);
    float4 a1 = make_float4(0.0f, 0.0f, 0.0f, 0.0f);
    acc_half4(a0, *(const uint2*)(g_xs + node * DD + lane * 4));  // self loop
    int j = 0;
    for (; j + 2 <= degc; j += 2) {
        int s0 = __ldg(&row[j]);
        int s1 = __ldg(&row[j + 1]);
        uint2 u0 = __ldg((const uint2*)(g_xs + s0 * DD + lane * 4));
        uint2 u1 = __ldg((const uint2*)(g_xs + s1 * DD + lane * 4));
        acc_half4(a0, u0);
        acc_half4(a1, u1);
    }
    if (j < degc) {
        int s = __ldg(&row[j]);
        uint2 u = __ldg((const uint2*)(g_xs + s * DD + lane * 4));
        acc_half4(a0, u);
    }

    const float dv = rsqrtf((float)(deg + 1));
    const float4 b = *(const float4*)(bias + lane * 4);
    float hx = fmaxf(dv * (a0.x + a1.x) + b.x, 0.0f);
    float hy = fmaxf(dv * (a0.y + a1.y) + b.y, 0.0f);
    float hz = fmaxf(dv * (a0.z + a1.z) + b.z, 0.0f);
    float hw = fmaxf(dv * (a0.w + a1.w) + b.w, 0.0f);
    uint2 u;
    u.x = h2_as_u32(__floats2half2_rn(hx, hy));
    u.y = h2_as_u32(__floats2half2_rn(hz, hw));
    *(uint2*)(g_h + node * DD + lane * 4) = u;
}

// --------------- mean-pool numerator over sorted batch ids (reads g_h) -------
__global__ void pool_kernel(const void* __restrict__ batch) {
    const int is64 = g_is64;
    const int c = threadIdx.x;  // 64 threads, one per feature
    const int start = blockIdx.x * 128;
    if (start >= NN) return;
    const int end = min(start + 128, NN);
    float acc = 0.f;
    int curg = load_idx(batch, start, is64);
    for (int i = start; i < end; i++) {
        int g = load_idx(batch, i, is64);
        if (g != curg) {
            atomicAdd(&g_pooled[curg * DD + c], acc);
            acc = 0.f; curg = g;
        }
        acc += __half2float(g_h[i * DD + c]);
    }
    atomicAdd(&g_pooled[curg * DD + c], acc);
}

// -------- head: counts via binary search (batch sorted) + FC + log_softmax ---
__device__ __forceinline__ int lower_bound_batch(const void* batch, int key, int is64) {
    int lo = 0, hi = NN;
    while (lo < hi) {
        int mid = (lo + hi) >> 1;
        if (load_idx(batch, mid, is64) < key) lo = mid + 1;
        else hi = mid;
    }
    return lo;
}

__global__ void head_kernel(const void* __restrict__ batch,
                            const float* __restrict__ Wfc,
                            const float* __restrict__ bfc,
                            float* __restrict__ out) {
    int g = threadIdx.x;
    if (g >= GG) return;
    const int is64 = g_is64;
    int c0 = lower_bound_batch(batch, g, is64);
    int c1 = lower_bound_batch(batch, g + 1, is64);
    float inv = 1.0f / fmaxf((float)(c1 - c0), 1.0f);

    float l0 = __ldg(&bfc[0]), l1 = __ldg(&bfc[1]);
#pragma unroll
    for (int k = 0; k < DD; k++) {
        float p = g_pooled[g * DD + k] * inv;
        l0 += p * __ldg(&Wfc[k * 2]);
        l1 += p * __ldg(&Wfc[k * 2 + 1]);
    }
    float m = fmaxf(l0, l1);
    float lse = m + logf(expf(l0 - m) + expf(l1 - m));
    out[g * 2 + 0] = l0 - lse;
    out[g * 2 + 1] = l1 - lse;
}

// ------------------------- launch --------------------------------------------
extern "C" void kernel_launch(void* const* d_in, const int* in_sizes, int n_in,
                              void* d_out, int out_size) {
    // Resolve inputs by element count (robust to metadata ordering).
    const float *x = 0, *W1 = 0, *b1 = 0, *W2 = 0, *b2 = 0, *Wfc = 0, *bfc = 0;
    const void *ei = 0, *batch = 0;
    for (int i = 0; i < n_in; i++) {
        int s = in_sizes[i];
        if (s == NN * DD)      x = (const float*)d_in[i];
        else if (s == 2 * EE)  ei = d_in[i];
        else if (s == NN)      batch = d_in[i];
        else if (s == DD * DD) { if (!W1) W1 = (const float*)d_in[i]; else W2 = (const float*)d_in[i]; }
        else if (s == DD)      { if (!b1) b1 = (const float*)d_in[i]; else b2 = (const float*)d_in[i]; }
        else if (s == DD * 2)  Wfc = (const float*)d_in[i];
        else if (s == 2)       bfc = (const float*)d_in[i];
    }
    float* out = (float*)d_out;

    // ncu's fixed window captures 0-based launch #3 -> gemm<true> (tensor).
    detect_kernel<<<1, 32>>>((const int*)ei);                  // 0
    zero_kernel<<<(NN + 255) / 256, 256>>>();                  // 1
    fillell_kernel<<<2048, 256>>>(ei);                         // 2
    gemm_kernel<true><<<(NN + 127) / 128, 256>>>(x, W1);       // 3  <- profiled
    gather_kernel<<<(NN * 16 + 255) / 256, 256>>>(b1);         // 4
    gemm_kernel<false><<<(NN + 127) / 128, 256>>>(nullptr, W2);// 5
    gather_kernel<<<(NN * 16 + 255) / 256, 256>>>(b2);         // 6
    pool_kernel<<<(NN + 127) / 128, 64>>>(batch);              // 7
    head_kernel<<<1, 64>>>(batch, Wfc, bfc, out);              // 8
}